// round 15
// baseline (speedup 1.0000x reference)
#include <cuda_runtime.h>

// Problem constants
#define NB 16
#define NC 3
#define H 768
#define W 768
#define HS 48            // H/16
#define WS 48            // W/16
#define NPIX (HS * WS)   // 2304
#define RADIUS 8

// exp(-(50*cd + 0.02*sd)) = exp2( -LOG2E*(50*cd + 0.02*sd) )
#define C_DOT   144.269504089f   // 2*50*log2(e)
#define C_SQ     72.134752044f   // 50*log2(e)
#define C_SP      0.028853901f   // 0.02*log2(e)

// Downsampled features: (f0, f1, f2, |f|^2) per (b, i). 16*2304*16B = 576 KB scratch.
__device__ float4 g_feats[NB * NPIX];

// ---------------------------------------------------------------------------
// Kernel 1: 16x bilinear downsample. Half-pixel centers => src = 16*i + 7.5,
// exact 0.5/0.5 weights => average of the 2x2 pixel block at (16y+7, 16x+7).
// Scalar loads only: x0 = 16*xi + 7 is ODD, so vector loads would misalign.
// Fires launch_dependents immediately so the PDL-chained affinity kernel
// can begin its feats-independent zero-store phase concurrently.
// ---------------------------------------------------------------------------
__global__ void resize_feats_kernel(const float* __restrict__ img) {
    asm volatile("griddepcontrol.launch_dependents;");

    int t = blockIdx.x * blockDim.x + threadIdx.x;
    if (t >= NB * NPIX) return;
    int b = t / NPIX;
    int i = t - b * NPIX;
    int yi = i / WS;
    int xi = i - yi * WS;
    int y0 = yi * 16 + 7;
    int x0 = xi * 16 + 7;

    float f[3];
#pragma unroll
    for (int c = 0; c < 3; ++c) {
        const float* p = img + ((size_t)(b * NC + c) * H + y0) * W + x0;
        // match separable resize: average rows first, then columns
        float r0 = 0.5f * (p[0] + p[1]);
        float r1 = 0.5f * (p[W] + p[W + 1]);
        f[c] = 0.5f * (r0 + r1);
    }
    float sq = f[0] * f[0] + f[1] * f[1] + f[2] * f[2];
    g_feats[t] = make_float4(f[0], f[1], f[2], sq);
}

__device__ __forceinline__ float ex2(float x) {
    float r;
    asm("ex2.approx.ftz.f32 %0, %1;" : "=f"(r) : "f"(x));
    return r;
}

// ---------------------------------------------------------------------------
// Kernel 2: affinity — R14 base + dx-sparsity early exit.
// Grid (144, 16): block bx handles rows i = bx + it*144, it = 0..15.
// Stride 144 == 3*WS => xi constant per block.
// The mask is 2-D: a row has only 17/2304 nonzero columns, so only the
// ~6/576 threads whose 4-column chunk overlaps xi +/- 8 ever produce a
// nonzero. Threads with NO dx overlap (anyok == false) write all 16 zero
// rows in phase 1 and EXIT before griddepcontrol.wait — no feats
// dependency, whole warps retire early, next wave's stores start sooner.
// Threads with overlap write out-of-band-dy zeros in phase 1, then wait,
// load fj invariants, and compute the <=6 in-band rows (3 FMA + EX2/elem).
// ---------------------------------------------------------------------------
__global__ void __launch_bounds__(576, 2) affinity_kernel(float* __restrict__ out) {
    const int q  = threadIdx.x;            // float4 index within row, 0..575
    const int bx = blockIdx.x;             // 0..143
    const int b  = blockIdx.y;             // 0..15

    const int j0  = q * 4;
    const int yj  = q / 12;                // shared by the 4 j's (4 | 48)
    const int xj0 = j0 - yj * WS;
    const int xi  = bx - (bx / WS) * WS;   // constant across all 16 rows

    const int dy0 = bx / WS - yj;          // row 0's dy; +3 per row
    const float4 zero = make_float4(0.f, 0.f, 0.f, 0.f);
    float4* const optr = (float4*)(out + (((size_t)b * NPIX + bx) * NPIX)) + q;
    const size_t ostride = (size_t)144 * (NPIX / 4);   // float4s per 144 rows

    // dx mask + spatial term (feats-independent).
    float sdx[4];
    bool  ok[4];
    bool  anyok = false;
#pragma unroll
    for (int k = 0; k < 4; ++k) {
        const int dx = xi - (xj0 + k);
        ok[k] = ((unsigned)(dx + RADIUS) <= 2u * RADIUS);
        anyok |= ok[k];
        sdx[k] = (float)(dx * dx);
    }

    // ---- Phase 1: all feats-independent zero stores (overlaps resize).
    // Threads with no dx overlap zero ALL 16 rows; others only out-of-band-dy.
#pragma unroll
    for (int it = 0; it < 16; ++it) {
        const int dy = dy0 + 3 * it;
        if (!anyok || (unsigned)(dy + RADIUS) > 2u * RADIUS)
            __stcs(optr + it * ostride, zero);
    }

    if (!anyok) return;                    // ~570/576 threads retire here

    // ---- Wait for resize's g_feats stores to be visible.
    asm volatile("griddepcontrol.wait;" ::: "memory");

    // ---- Phase 2: in-band rows (only ~6 threads/block reach this).
    const float4* __restrict__ frow = g_feats + b * NPIX;

    float fjx[4], fjy[4], fjz[4], CK[4];
#pragma unroll
    for (int k = 0; k < 4; ++k) {
        const float4 fj = frow[j0 + k];
        fjx[k] = C_DOT * fj.x;
        fjy[k] = C_DOT * fj.y;
        fjz[k] = C_DOT * fj.z;
        CK[k]  = -C_SQ * fj.w - C_SP * sdx[k];
    }

#pragma unroll
    for (int it = 0; it < 16; ++it) {
        const int dy = dy0 + 3 * it;
        if ((unsigned)(dy + RADIUS) <= 2u * RADIUS) {
            const float4 fi = frow[bx + it * 144];
            const float  DI = -C_SQ * fi.w - C_SP * (float)(dy * dy);
            float4 v = zero;
            float* vv = (float*)&v;
#pragma unroll
            for (int k = 0; k < 4; ++k) {
                if (ok[k]) {
                    float t = fmaf(fjx[k], fi.x, CK[k]);
                    t = fmaf(fjy[k], fi.y, t);
                    t = fmaf(fjz[k], fi.z, t);
                    vv[k] = ex2(t + DI);
                }
            }
            __stcs(optr + it * ostride, v);
        }
    }
}

// ---------------------------------------------------------------------------
extern "C" void kernel_launch(void* const* d_in, const int* in_sizes, int n_in,
                              void* d_out, int out_size) {
    const float* img = (const float*)d_in[0];
    float* out = (float*)d_out;

    const int nfeat = NB * NPIX;
    resize_feats_kernel<<<(nfeat + 255) / 256, 256>>>(img);

    // Affinity chained via Programmatic Dependent Launch: launches while
    // resize runs; griddepcontrol.wait inside orders the g_feats reads.
    cudaLaunchConfig_t cfg = {};
    cfg.gridDim  = dim3(144, NB);
    cfg.blockDim = dim3(576);
    cudaLaunchAttribute attr[1];
    attr[0].id = cudaLaunchAttributeProgrammaticStreamSerialization;
    attr[0].val.programmaticStreamSerializationAllowed = 1;
    cfg.attrs = attr;
    cfg.numAttrs = 1;
    cudaLaunchKernelEx(&cfg, affinity_kernel, out);
}

// round 16
// speedup vs baseline: 1.2290x; 1.2290x over previous
#include <cuda_runtime.h>

// Problem constants
#define NB 16
#define NC 3
#define H 768
#define W 768
#define HS 48            // H/16
#define WS 48            // W/16
#define NPIX (HS * WS)   // 2304
#define RADIUS 8

// exp(-(50*cd + 0.02*sd)) = exp2( -LOG2E*(50*cd + 0.02*sd) )
#define C_DOT   144.269504089f   // 2*50*log2(e)
#define C_SQ     72.134752044f   // 50*log2(e)
#define C_SP      0.028853901f   // 0.02*log2(e)

// Downsampled features: (f0, f1, f2, |f|^2) per (b, i). 16*2304*16B = 576 KB scratch.
__device__ float4 g_feats[NB * NPIX];

// ---------------------------------------------------------------------------
// Kernel 1: 16x bilinear downsample. Half-pixel centers => src = 16*i + 7.5,
// exact 0.5/0.5 weights => average of the 2x2 pixel block at (16y+7, 16x+7).
// Scalar loads only: x0 = 16*xi + 7 is ODD, so vector loads would misalign.
// Fires launch_dependents immediately so the PDL-chained affinity kernel
// can begin its feats-independent zero-store phase concurrently.
// ---------------------------------------------------------------------------
__global__ void resize_feats_kernel(const float* __restrict__ img) {
    asm volatile("griddepcontrol.launch_dependents;");

    int t = blockIdx.x * blockDim.x + threadIdx.x;
    if (t >= NB * NPIX) return;
    int b = t / NPIX;
    int i = t - b * NPIX;
    int yi = i / WS;
    int xi = i - yi * WS;
    int y0 = yi * 16 + 7;
    int x0 = xi * 16 + 7;

    float f[3];
#pragma unroll
    for (int c = 0; c < 3; ++c) {
        const float* p = img + ((size_t)(b * NC + c) * H + y0) * W + x0;
        // match separable resize: average rows first, then columns
        float r0 = 0.5f * (p[0] + p[1]);
        float r1 = 0.5f * (p[W] + p[W + 1]);
        f[c] = 0.5f * (r0 + r1);
    }
    float sq = f[0] * f[0] + f[1] * f[1] + f[2] * f[2];
    g_feats[t] = make_float4(f[0], f[1], f[2], sq);
}

__device__ __forceinline__ float ex2(float x) {
    float r;
    asm("ex2.approx.ftz.f32 %0, %1;" : "=f"(r) : "f"(x));
    return r;
}

// ---------------------------------------------------------------------------
// Kernel 2: affinity — converged configuration (R14, best measured 51.7us).
// Grid (144, 16): block bx handles rows i = bx + it*144, it = 0..15.
// Stride 144 == 3*WS => xi constant per block.
// Phase 1 (before griddepcontrol.wait): the ~10/16 out-of-band rows per
// thread depend only on dy -> issue their zero STG.128s while the resize
// kernel is still running (PDL overlap), pre-filling the DRAM write pipe.
// The dy predicate is near-uniform across each warp (consecutive q share
// yj), so every unrolled iteration issues full-warp coalesced wavefronts —
// do NOT add per-lane (dx-dependent) predicates here (R15 regression).
// Phase 2 (after wait): load fj invariants (pre-scaled fj', exponent
// constant CK, band mask) once, then in-band rows at 3 FMA + FADD + EX2
// per element with streaming STG.128.
// Replay period is DRAM-write limited: 340 MB @ ~6.6 TB/s = ~51.7 us.
// ---------------------------------------------------------------------------
__global__ void __launch_bounds__(576, 2) affinity_kernel(float* __restrict__ out) {
    const int q  = threadIdx.x;            // float4 index within row, 0..575
    const int bx = blockIdx.x;             // 0..143
    const int b  = blockIdx.y;             // 0..15

    const int j0  = q * 4;
    const int yj  = q / 12;                // shared by the 4 j's (4 | 48)
    const int xj0 = j0 - yj * WS;
    const int xi  = bx - (bx / WS) * WS;   // constant across all 16 rows

    const int dy0 = bx / WS - yj;          // row 0's dy; +3 per row
    const float4 zero = make_float4(0.f, 0.f, 0.f, 0.f);
    float4* const optr = (float4*)(out + (((size_t)b * NPIX + bx) * NPIX)) + q;
    const size_t ostride = (size_t)144 * (NPIX / 4);   // float4s per 144 rows

    // ---- Phase 1: feats-independent zero stores (overlaps resize via PDL).
#pragma unroll
    for (int it = 0; it < 16; ++it) {
        const int dy = dy0 + 3 * it;
        if ((unsigned)(dy + RADIUS) > 2u * RADIUS)
            __stcs(optr + it * ostride, zero);
    }

    // ---- Wait for resize's g_feats stores to be visible.
    asm volatile("griddepcontrol.wait;" ::: "memory");

    // ---- Phase 2: in-band rows.
    const float4* __restrict__ frow = g_feats + b * NPIX;

    float fjx[4], fjy[4], fjz[4], CK[4];
    bool  ok[4];
#pragma unroll
    for (int k = 0; k < 4; ++k) {
        const int dx = xi - (xj0 + k);
        ok[k] = ((unsigned)(dx + RADIUS) <= 2u * RADIUS);
        const float4 fj = frow[j0 + k];
        fjx[k] = C_DOT * fj.x;
        fjy[k] = C_DOT * fj.y;
        fjz[k] = C_DOT * fj.z;
        CK[k]  = -C_SQ * fj.w - C_SP * (float)(dx * dx);
    }

#pragma unroll
    for (int it = 0; it < 16; ++it) {
        const int dy = dy0 + 3 * it;
        if ((unsigned)(dy + RADIUS) <= 2u * RADIUS) {
            const float4 fi = frow[bx + it * 144];
            const float  DI = -C_SQ * fi.w - C_SP * (float)(dy * dy);
            float4 v = zero;
            float* vv = (float*)&v;
#pragma unroll
            for (int k = 0; k < 4; ++k) {
                if (ok[k]) {
                    float t = fmaf(fjx[k], fi.x, CK[k]);
                    t = fmaf(fjy[k], fi.y, t);
                    t = fmaf(fjz[k], fi.z, t);
                    vv[k] = ex2(t + DI);
                }
            }
            __stcs(optr + it * ostride, v);
        }
    }
}

// ---------------------------------------------------------------------------
extern "C" void kernel_launch(void* const* d_in, const int* in_sizes, int n_in,
                              void* d_out, int out_size) {
    const float* img = (const float*)d_in[0];
    float* out = (float*)d_out;

    const int nfeat = NB * NPIX;
    resize_feats_kernel<<<(nfeat + 255) / 256, 256>>>(img);

    // Affinity chained via Programmatic Dependent Launch: launches while
    // resize runs; griddepcontrol.wait inside orders the g_feats reads.
    cudaLaunchConfig_t cfg = {};
    cfg.gridDim  = dim3(144, NB);
    cfg.blockDim = dim3(576);
    cudaLaunchAttribute attr[1];
    attr[0].id = cudaLaunchAttributeProgrammaticStreamSerialization;
    attr[0].val.programmaticStreamSerializationAllowed = 1;
    cfg.attrs = attr;
    cfg.numAttrs = 1;
    cudaLaunchKernelEx(&cfg, affinity_kernel, out);
}